// round 1
// baseline (speedup 1.0000x reference)
#include <cuda_runtime.h>
#include <math.h>

#define NN 100000
#define EE 1600000
#define DD 128
#define LL 4
#define GG 512
#define BN_EPS 1e-5f

// ---------------- device scratch (no allocations allowed) ----------------
static __device__ __align__(16) float g_h[(size_t)NN * DD];   // current node features
static __device__ __align__(16) float g_z[(size_t)NN * DD];   // h + aggregated neighbors
static __device__ __align__(16) float g_y[(size_t)NN * DD];   // GEMM1 output (pre-BN)
static __device__ float g_colsum[DD];
static __device__ float g_colsumsq[DD];
static __device__ float g_scale[DD];
static __device__ float g_shift[DD];
static __device__ __align__(16) float g_pool[GG * DD];
static __device__ float g_cnt[GG];

__device__ __forceinline__ float elu_f(float x) {
    return x > 0.f ? x : expm1f(x);
}

// ---------------- small utility kernels ----------------
__global__ void copy_x_to_h(const float4* __restrict__ x) {
    int i = blockIdx.x * blockDim.x + threadIdx.x;
    if (i < NN * DD / 4) ((float4*)g_h)[i] = x[i];
}

__global__ void copy_h_to_z() {
    int i = blockIdx.x * blockDim.x + threadIdx.x;
    if (i < NN * DD / 4) ((float4*)g_z)[i] = ((const float4*)g_h)[i];
}

__global__ void zero_stats() {
    int t = threadIdx.x;
    if (t < DD) { g_colsum[t] = 0.f; g_colsumsq[t] = 0.f; }
}

__global__ void zero_pool() {
    int i = blockIdx.x * blockDim.x + threadIdx.x;
    if (i < GG * DD) g_pool[i] = 0.f;
    if (i < GG) g_cnt[i] = 0.f;
}

// ---------------- edge scatter-add: z[dst] += h[src] ----------------
// one warp per edge; each lane handles a float4 chunk of the 128-dim row
__global__ void scatter_kernel(const int* __restrict__ ei) {
    long tid = (long)blockIdx.x * blockDim.x + threadIdx.x;
    if (tid >= (long)EE * 32) return;
    int e = (int)(tid >> 5);
    int c = (int)(tid & 31) << 2;
    int src = __ldg(&ei[e]);
    int dst = __ldg(&ei[EE + e]);
    float4 v = *(const float4*)&g_h[(size_t)src * DD + c];
    float* p = &g_z[(size_t)dst * DD + c];
    atomicAdd(p + 0, v.x);
    atomicAdd(p + 1, v.y);
    atomicAdd(p + 2, v.z);
    atomicAdd(p + 3, v.w);
}

// ---------------- fused GEMM ----------------
// MODE 0: C(g_y) = A(g_z) @ B + bias, epilogue accumulates per-column sum/sumsq
// MODE 1: A' = elu(g_y * scale + shift) applied on load; C(g_h) = elu(A' @ B + bias)
// Tile: BM=64, BN=128, BK=32, 256 threads, thread tile 8x4.
template <int MODE>
__global__ __launch_bounds__(256) void gemm_kernel(const float* __restrict__ B,
                                                   const float* __restrict__ bias) {
    __shared__ float As[64][36];     // padded stride: 36*4=144B rows, float4-aligned
    __shared__ float Bs[32][128];
    __shared__ float s_sum[DD];
    __shared__ float s_sq[DD];

    const float* A = (MODE == 0) ? g_z : g_y;
    float* C = (MODE == 0) ? g_y : g_h;

    const int tid = threadIdx.x;
    const int tm = tid >> 5;        // 0..7
    const int tn = tid & 31;        // 0..31
    const int rowBase = blockIdx.x * 64;

    if (MODE == 0 && tid < DD) { s_sum[tid] = 0.f; s_sq[tid] = 0.f; }

    float acc[8][4];
#pragma unroll
    for (int i = 0; i < 8; i++)
#pragma unroll
        for (int j = 0; j < 4; j++) acc[i][j] = 0.f;

    for (int k0 = 0; k0 < DD; k0 += 32) {
        // load A tile (64x32), zero-fill OOB rows, MODE1 applies affine+ELU
#pragma unroll
        for (int i = 0; i < 2; i++) {
            int f = tid + i * 256;
            int r = f >> 3;
            int c4 = (f & 7) << 2;
            int gr = rowBase + r;
            float4 v = make_float4(0.f, 0.f, 0.f, 0.f);
            if (gr < NN) {
                v = *(const float4*)&A[(size_t)gr * DD + k0 + c4];
                if (MODE == 1) {
                    int col = k0 + c4;
                    v.x = elu_f(v.x * g_scale[col + 0] + g_shift[col + 0]);
                    v.y = elu_f(v.y * g_scale[col + 1] + g_shift[col + 1]);
                    v.z = elu_f(v.z * g_scale[col + 2] + g_shift[col + 2]);
                    v.w = elu_f(v.w * g_scale[col + 3] + g_shift[col + 3]);
                }
            }
            *(float4*)&As[r][c4] = v;
        }
        // load B tile (32x128)
#pragma unroll
        for (int i = 0; i < 4; i++) {
            int f = tid + i * 256;
            int r = f >> 5;
            int c4 = (f & 31) << 2;
            *(float4*)&Bs[r][c4] = *(const float4*)&B[(size_t)(k0 + r) * DD + c4];
        }
        __syncthreads();

#pragma unroll
        for (int kk = 0; kk < 32; kk++) {
            float a[8];
#pragma unroll
            for (int i = 0; i < 8; i++) a[i] = As[tm * 8 + i][kk];
            float4 bv = *(float4*)&Bs[kk][tn * 4];
            float b[4] = {bv.x, bv.y, bv.z, bv.w};
#pragma unroll
            for (int i = 0; i < 8; i++)
#pragma unroll
                for (int j = 0; j < 4; j++) acc[i][j] += a[i] * b[j];
        }
        __syncthreads();
    }

    float bv0 = bias[tn * 4 + 0];
    float bv1 = bias[tn * 4 + 1];
    float bv2 = bias[tn * 4 + 2];
    float bv3 = bias[tn * 4 + 3];

    if (MODE == 0) {
        float ps[4] = {0.f, 0.f, 0.f, 0.f};
        float pq[4] = {0.f, 0.f, 0.f, 0.f};
#pragma unroll
        for (int i = 0; i < 8; i++) {
            int gr = rowBase + tm * 8 + i;
            if (gr < NN) {
                float4 o;
                o.x = acc[i][0] + bv0;
                o.y = acc[i][1] + bv1;
                o.z = acc[i][2] + bv2;
                o.w = acc[i][3] + bv3;
                *(float4*)&C[(size_t)gr * DD + tn * 4] = o;
                ps[0] += o.x; ps[1] += o.y; ps[2] += o.z; ps[3] += o.w;
                pq[0] += o.x * o.x; pq[1] += o.y * o.y;
                pq[2] += o.z * o.z; pq[3] += o.w * o.w;
            }
        }
#pragma unroll
        for (int j = 0; j < 4; j++) {
            atomicAdd(&s_sum[tn * 4 + j], ps[j]);
            atomicAdd(&s_sq[tn * 4 + j], pq[j]);
        }
        __syncthreads();
        if (tid < DD) {
            atomicAdd(&g_colsum[tid], s_sum[tid]);
            atomicAdd(&g_colsumsq[tid], s_sq[tid]);
        }
    } else {
#pragma unroll
        for (int i = 0; i < 8; i++) {
            int gr = rowBase + tm * 8 + i;
            if (gr < NN) {
                float4 o;
                o.x = elu_f(acc[i][0] + bv0);
                o.y = elu_f(acc[i][1] + bv1);
                o.z = elu_f(acc[i][2] + bv2);
                o.w = elu_f(acc[i][3] + bv3);
                *(float4*)&C[(size_t)gr * DD + tn * 4] = o;
            }
        }
    }
}

// ---------------- BN finalize: per-column scale/shift ----------------
__global__ void bn_finalize(const float* __restrict__ gamma, const float* __restrict__ beta) {
    int t = threadIdx.x;
    if (t >= DD) return;
    float mu = g_colsum[t] / (float)NN;
    float var = fmaxf(g_colsumsq[t] / (float)NN - mu * mu, 0.f);
    float rs = rsqrtf(var + BN_EPS);
    float sc = rs * gamma[t];
    g_scale[t] = sc;
    g_shift[t] = beta[t] - mu * sc;
}

// ---------------- pooling ----------------
__global__ void pool_kernel(const int* __restrict__ batch) {
    long tid = (long)blockIdx.x * blockDim.x + threadIdx.x;
    if (tid >= (long)NN * 32) return;
    int i = (int)(tid >> 5);
    int c = (int)(tid & 31) << 2;
    int g = __ldg(&batch[i]);
    float4 v = *(const float4*)&g_h[(size_t)i * DD + c];
    float* p = &g_pool[g * DD + c];
    atomicAdd(p + 0, v.x);
    atomicAdd(p + 1, v.y);
    atomicAdd(p + 2, v.z);
    atomicAdd(p + 3, v.w);
}

__global__ void count_kernel(const int* __restrict__ batch) {
    int i = blockIdx.x * blockDim.x + threadIdx.x;
    if (i >= NN) return;
    int g = batch[i];
    unsigned mask = __match_any_sync(__activemask(), g);
    int leader = __ffs(mask) - 1;
    if ((threadIdx.x & 31) == leader)
        atomicAdd(&g_cnt[g], (float)__popc(mask));
}

// ---------------- final: pooled mean @ lin_W + lin_b ----------------
__global__ void final_kernel(const float* __restrict__ linW,
                             const float* __restrict__ linb,
                             float* __restrict__ out) {
    int g = blockIdx.x;
    int t = threadIdx.x;  // 128 threads
    float cnt = fmaxf(g_cnt[g], 1.f);
    float p = g_pool[g * DD + t] / cnt;
    float v0 = p * __ldg(&linW[t * 2 + 0]);
    float v1 = p * __ldg(&linW[t * 2 + 1]);
#pragma unroll
    for (int o = 16; o > 0; o >>= 1) {
        v0 += __shfl_down_sync(0xffffffffu, v0, o);
        v1 += __shfl_down_sync(0xffffffffu, v1, o);
    }
    __shared__ float s0[4], s1[4];
    if ((t & 31) == 0) { s0[t >> 5] = v0; s1[t >> 5] = v1; }
    __syncthreads();
    if (t == 0) {
        out[g * 2 + 0] = s0[0] + s0[1] + s0[2] + s0[3] + linb[0];
        out[g * 2 + 1] = s1[0] + s1[1] + s1[2] + s1[3] + linb[1];
    }
}

// ---------------- launch ----------------
extern "C" void kernel_launch(void* const* d_in, const int* in_sizes, int n_in,
                              void* d_out, int out_size) {
    const float* x     = (const float*)d_in[0];
    const int*   ei    = (const int*)d_in[1];
    const int*   batch = (const int*)d_in[2];
    const float* W1    = (const float*)d_in[3];
    const float* b1    = (const float*)d_in[4];
    const float* gamma = (const float*)d_in[5];
    const float* beta  = (const float*)d_in[6];
    const float* W2    = (const float*)d_in[7];
    const float* b2    = (const float*)d_in[8];
    const float* linW  = (const float*)d_in[9];
    const float* linb  = (const float*)d_in[10];
    float* out = (float*)d_out;

    const int copyBlocks = (NN * DD / 4 + 255) / 256;
    const int scatBlocks = (int)(((long)EE * 32 + 255) / 256);
    const int gemmBlocks = (NN + 63) / 64;
    const int poolBlocks = (int)(((long)NN * 32 + 255) / 256);

    copy_x_to_h<<<copyBlocks, 256>>>((const float4*)x);

    for (int l = 0; l < LL; l++) {
        copy_h_to_z<<<copyBlocks, 256>>>();
        scatter_kernel<<<scatBlocks, 256>>>(ei);
        zero_stats<<<1, 256>>>();
        gemm_kernel<0><<<gemmBlocks, 256>>>(W1 + (size_t)l * DD * DD, b1 + l * DD);
        bn_finalize<<<1, 128>>>(gamma + l * DD, beta + l * DD);
        gemm_kernel<1><<<gemmBlocks, 256>>>(W2 + (size_t)l * DD * DD, b2 + l * DD);
    }

    zero_pool<<<(GG * DD + 255) / 256, 256>>>();
    pool_kernel<<<poolBlocks, 256>>>(batch);
    count_kernel<<<(NN + 255) / 256, 256>>>(batch);
    final_kernel<<<GG, 128>>>(linW, linb, out);
}

// round 2
// speedup vs baseline: 1.5679x; 1.5679x over previous
#include <cuda_runtime.h>
#include <math.h>

#define NN 100000
#define EE 1600000
#define DD 128
#define LL 4
#define GG 512
#define BN_EPS 1e-5f

// ---------------- device scratch (no allocations allowed) ----------------
static __device__ __align__(16) float g_h[(size_t)NN * DD];   // current node features
static __device__ __align__(16) float g_z[(size_t)NN * DD];   // h + aggregated neighbors
static __device__ __align__(16) float g_y[(size_t)NN * DD];   // GEMM1 output (pre-BN)
static __device__ float g_colsum[DD];
static __device__ float g_colsumsq[DD];
static __device__ float g_scale[DD];
static __device__ float g_shift[DD];
static __device__ __align__(16) float g_pool[GG * DD];
static __device__ float g_cnt[GG];

__device__ __forceinline__ float elu_f(float x) {
    return x > 0.f ? x : expm1f(x);
}

__device__ __forceinline__ void red_add_v4(float* p, float4 v) {
    asm volatile("red.global.add.v4.f32 [%0], {%1,%2,%3,%4};"
                 :: "l"(p), "f"(v.x), "f"(v.y), "f"(v.z), "f"(v.w) : "memory");
}

// ---------------- small utility kernels ----------------
__global__ void copy_x_to_h(const float4* __restrict__ x) {
    int i = blockIdx.x * blockDim.x + threadIdx.x;
    if (i < NN * DD / 4) ((float4*)g_h)[i] = x[i];
}

__global__ void copy_h_to_z() {
    int i = blockIdx.x * blockDim.x + threadIdx.x;
    if (i < NN * DD / 4) ((float4*)g_z)[i] = ((const float4*)g_h)[i];
}

__global__ void zero_stats() {
    int t = threadIdx.x;
    if (t < DD) { g_colsum[t] = 0.f; g_colsumsq[t] = 0.f; }
}

__global__ void zero_pool() {
    int i = blockIdx.x * blockDim.x + threadIdx.x;
    if (i < GG * DD) g_pool[i] = 0.f;
    if (i < GG) g_cnt[i] = 0.f;
}

// ---------------- edge scatter-add: z[dst] += h[src] ----------------
// one warp per edge; each lane handles a float4 chunk of the 128-dim row
__global__ void scatter_kernel(const int* __restrict__ ei) {
    long tid = (long)blockIdx.x * blockDim.x + threadIdx.x;
    if (tid >= (long)EE * 32) return;
    int e = (int)(tid >> 5);
    int c = (int)(tid & 31) << 2;
    int src = __ldg(&ei[e]);
    int dst = __ldg(&ei[EE + e]);
    float4 v = *(const float4*)&g_h[(size_t)src * DD + c];
    red_add_v4(&g_z[(size_t)dst * DD + c], v);
}

// ---------------- fused GEMM ----------------
// MODE 0: C(g_y) = A(g_z) @ B + bias, epilogue accumulates per-column sum/sumsq
// MODE 1: A' = elu(g_y * scale + shift) applied on load; C(g_h) = elu(A' @ B + bias)
// Tile: BM=128, BN=128, BK=16, 256 threads, 8x8 microtile split as {q*4, 64+q*4}.
template <int MODE>
__global__ __launch_bounds__(256) void gemm_kernel(const float* __restrict__ B,
                                                   const float* __restrict__ bias) {
    __shared__ float As[16][132];     // transposed A tile, padded
    __shared__ float Bs[16][132];
    __shared__ float s_sum[DD];
    __shared__ float s_sq[DD];

    const float* A = (MODE == 0) ? g_z : g_y;
    float* C = (MODE == 0) ? g_y : g_h;

    const int tid = threadIdx.x;
    const int tm = tid >> 4;        // 0..15
    const int tn = tid & 15;        // 0..15
    const int rowBase = blockIdx.x * 128;

    if (MODE == 0 && tid < DD) { s_sum[tid] = 0.f; s_sq[tid] = 0.f; }

    float acc[8][8];
#pragma unroll
    for (int i = 0; i < 8; i++)
#pragma unroll
        for (int j = 0; j < 8; j++) acc[i][j] = 0.f;

    for (int k0 = 0; k0 < DD; k0 += 16) {
        // load A tile (128 rows x 16 k), transpose into As[k][row]
#pragma unroll
        for (int i = 0; i < 2; i++) {
            int f = tid + i * 256;          // 0..511
            int r = f >> 2;                 // 0..127
            int c4 = (f & 3) << 2;          // 0,4,8,12
            int gr = rowBase + r;
            float4 v = make_float4(0.f, 0.f, 0.f, 0.f);
            if (gr < NN) {
                v = *(const float4*)&A[(size_t)gr * DD + k0 + c4];
                if (MODE == 1) {
                    int col = k0 + c4;
                    v.x = elu_f(v.x * g_scale[col + 0] + g_shift[col + 0]);
                    v.y = elu_f(v.y * g_scale[col + 1] + g_shift[col + 1]);
                    v.z = elu_f(v.z * g_scale[col + 2] + g_shift[col + 2]);
                    v.w = elu_f(v.w * g_scale[col + 3] + g_shift[col + 3]);
                }
            }
            As[c4 + 0][r] = v.x;
            As[c4 + 1][r] = v.y;
            As[c4 + 2][r] = v.z;
            As[c4 + 3][r] = v.w;
        }
        // load B tile (16 k x 128 n)
#pragma unroll
        for (int i = 0; i < 2; i++) {
            int f = tid + i * 256;          // 0..511
            int r = f >> 5;                 // 0..15
            int c4 = (f & 31) << 2;
            *(float4*)&Bs[r][c4] = *(const float4*)&B[(size_t)(k0 + r) * DD + c4];
        }
        __syncthreads();

#pragma unroll
        for (int kk = 0; kk < 16; kk++) {
            float4 a0 = *(float4*)&As[kk][tm * 4];
            float4 a1 = *(float4*)&As[kk][64 + tm * 4];
            float4 b0 = *(float4*)&Bs[kk][tn * 4];
            float4 b1 = *(float4*)&Bs[kk][64 + tn * 4];
            float a[8] = {a0.x, a0.y, a0.z, a0.w, a1.x, a1.y, a1.z, a1.w};
            float b[8] = {b0.x, b0.y, b0.z, b0.w, b1.x, b1.y, b1.z, b1.w};
#pragma unroll
            for (int i = 0; i < 8; i++)
#pragma unroll
                for (int j = 0; j < 8; j++) acc[i][j] += a[i] * b[j];
        }
        __syncthreads();
    }

    // column indices for this thread: cols[j] = tn*4+j (j<4), 64+tn*4+j-4 (j>=4)
    float bv[8];
#pragma unroll
    for (int j = 0; j < 8; j++) {
        int col = (j < 4) ? (tn * 4 + j) : (64 + tn * 4 + j - 4);
        bv[j] = bias[col];
    }

    if (MODE == 0) {
        float ps[8], pq[8];
#pragma unroll
        for (int j = 0; j < 8; j++) { ps[j] = 0.f; pq[j] = 0.f; }
#pragma unroll
        for (int i = 0; i < 8; i++) {
            int gr = rowBase + ((i < 4) ? (tm * 4 + i) : (64 + tm * 4 + i - 4));
            if (gr < NN) {
                float o[8];
#pragma unroll
                for (int j = 0; j < 8; j++) {
                    o[j] = acc[i][j] + bv[j];
                    ps[j] += o[j];
                    pq[j] += o[j] * o[j];
                }
                *(float4*)&C[(size_t)gr * DD + tn * 4]      = make_float4(o[0], o[1], o[2], o[3]);
                *(float4*)&C[(size_t)gr * DD + 64 + tn * 4] = make_float4(o[4], o[5], o[6], o[7]);
            }
        }
#pragma unroll
        for (int j = 0; j < 8; j++) {
            int col = (j < 4) ? (tn * 4 + j) : (64 + tn * 4 + j - 4);
            atomicAdd(&s_sum[col], ps[j]);
            atomicAdd(&s_sq[col], pq[j]);
        }
        __syncthreads();
        if (tid < DD) {
            atomicAdd(&g_colsum[tid], s_sum[tid]);
            atomicAdd(&g_colsumsq[tid], s_sq[tid]);
        }
    } else {
#pragma unroll
        for (int i = 0; i < 8; i++) {
            int gr = rowBase + ((i < 4) ? (tm * 4 + i) : (64 + tm * 4 + i - 4));
            if (gr < NN) {
                float o[8];
#pragma unroll
                for (int j = 0; j < 8; j++) o[j] = elu_f(acc[i][j] + bv[j]);
                *(float4*)&C[(size_t)gr * DD + tn * 4]      = make_float4(o[0], o[1], o[2], o[3]);
                *(float4*)&C[(size_t)gr * DD + 64 + tn * 4] = make_float4(o[4], o[5], o[6], o[7]);
            }
        }
    }
}

// ---------------- BN finalize: per-column scale/shift ----------------
__global__ void bn_finalize(const float* __restrict__ gamma, const float* __restrict__ beta) {
    int t = threadIdx.x;
    if (t >= DD) return;
    float mu = g_colsum[t] / (float)NN;
    float var = fmaxf(g_colsumsq[t] / (float)NN - mu * mu, 0.f);
    float rs = rsqrtf(var + BN_EPS);
    float sc = rs * gamma[t];
    g_scale[t] = sc;
    g_shift[t] = beta[t] - mu * sc;
}

// ---------------- pooling ----------------
__global__ void pool_kernel(const int* __restrict__ batch) {
    long tid = (long)blockIdx.x * blockDim.x + threadIdx.x;
    if (tid >= (long)NN * 32) return;
    int i = (int)(tid >> 5);
    int c = (int)(tid & 31) << 2;
    int g = __ldg(&batch[i]);
    float4 v = *(const float4*)&g_h[(size_t)i * DD + c];
    red_add_v4(&g_pool[g * DD + c], v);
}

__global__ void count_kernel(const int* __restrict__ batch) {
    int i = blockIdx.x * blockDim.x + threadIdx.x;
    if (i >= NN) return;
    int g = batch[i];
    unsigned mask = __match_any_sync(__activemask(), g);
    int leader = __ffs(mask) - 1;
    if ((threadIdx.x & 31) == leader)
        atomicAdd(&g_cnt[g], (float)__popc(mask));
}

// ---------------- final: pooled mean @ lin_W + lin_b ----------------
__global__ void final_kernel(const float* __restrict__ linW,
                             const float* __restrict__ linb,
                             float* __restrict__ out) {
    int g = blockIdx.x;
    int t = threadIdx.x;  // 128 threads
    float cnt = fmaxf(g_cnt[g], 1.f);
    float p = g_pool[g * DD + t] / cnt;
    float v0 = p * __ldg(&linW[t * 2 + 0]);
    float v1 = p * __ldg(&linW[t * 2 + 1]);
#pragma unroll
    for (int o = 16; o > 0; o >>= 1) {
        v0 += __shfl_down_sync(0xffffffffu, v0, o);
        v1 += __shfl_down_sync(0xffffffffu, v1, o);
    }
    __shared__ float s0[4], s1[4];
    if ((t & 31) == 0) { s0[t >> 5] = v0; s1[t >> 5] = v1; }
    __syncthreads();
    if (t == 0) {
        out[g * 2 + 0] = s0[0] + s0[1] + s0[2] + s0[3] + linb[0];
        out[g * 2 + 1] = s1[0] + s1[1] + s1[2] + s1[3] + linb[1];
    }
}

// ---------------- launch ----------------
extern "C" void kernel_launch(void* const* d_in, const int* in_sizes, int n_in,
                              void* d_out, int out_size) {
    const float* x     = (const float*)d_in[0];
    const int*   ei    = (const int*)d_in[1];
    const int*   batch = (const int*)d_in[2];
    const float* W1    = (const float*)d_in[3];
    const float* b1    = (const float*)d_in[4];
    const float* gamma = (const float*)d_in[5];
    const float* beta  = (const float*)d_in[6];
    const float* W2    = (const float*)d_in[7];
    const float* b2    = (const float*)d_in[8];
    const float* linW  = (const float*)d_in[9];
    const float* linb  = (const float*)d_in[10];
    float* out = (float*)d_out;

    const int copyBlocks = (NN * DD / 4 + 255) / 256;
    const int scatBlocks = (int)(((long)EE * 32 + 255) / 256);
    const int gemmBlocks = (NN + 127) / 128;
    const int poolBlocks = (int)(((long)NN * 32 + 255) / 256);

    copy_x_to_h<<<copyBlocks, 256>>>((const float4*)x);

    for (int l = 0; l < LL; l++) {
        copy_h_to_z<<<copyBlocks, 256>>>();
        scatter_kernel<<<scatBlocks, 256>>>(ei);
        zero_stats<<<1, 256>>>();
        gemm_kernel<0><<<gemmBlocks, 256>>>(W1 + (size_t)l * DD * DD, b1 + l * DD);
        bn_finalize<<<1, 128>>>(gamma + l * DD, beta + l * DD);
        gemm_kernel<1><<<gemmBlocks, 256>>>(W2 + (size_t)l * DD * DD, b2 + l * DD);
    }

    zero_pool<<<(GG * DD + 255) / 256, 256>>>();
    pool_kernel<<<poolBlocks, 256>>>(batch);
    count_kernel<<<(NN + 255) / 256, 256>>>(batch);
    final_kernel<<<GG, 128>>>(linW, linb, out);
}

// round 3
// speedup vs baseline: 2.5364x; 1.6178x over previous
#include <cuda_runtime.h>
#include <math.h>

#define NN 100000
#define EE 1600000
#define DD 128
#define LL 4
#define GG 512
#define BN_EPS 1e-5f

typedef unsigned long long ull;

// ---------------- device scratch (no allocations allowed) ----------------
static __device__ __align__(16) float g_h[(size_t)NN * DD];   // current node features
static __device__ __align__(16) float g_z[(size_t)NN * DD];   // h + aggregated neighbors
static __device__ __align__(16) float g_y[(size_t)NN * DD];   // GEMM1 output (pre-BN)
static __device__ float g_colsum[DD];
static __device__ float g_colsumsq[DD];
static __device__ float g_scale[DD];
static __device__ float g_shift[DD];
// CSR scratch
static __device__ int g_deg[NN];
static __device__ int g_rowptr[NN + 1];
static __device__ int g_cursor[NN];
static __device__ int g_csr_src[EE];
static __device__ int g_bsum[256];
static __device__ int g_boff[256];

#define SCAN_BLK 512
#define NBLK_SCAN ((NN + SCAN_BLK - 1) / SCAN_BLK)   // 196

__device__ __forceinline__ float elu_f(float x) {
    return x > 0.f ? x : expm1f(x);
}

// ---------------- small utility kernels ----------------
__global__ void copy_x_to_h(const float4* __restrict__ x) {
    int i = blockIdx.x * blockDim.x + threadIdx.x;
    if (i < NN * DD / 4) ((float4*)g_h)[i] = x[i];
}

__global__ void zero_stats() {
    int t = threadIdx.x;
    if (t < DD) { g_colsum[t] = 0.f; g_colsumsq[t] = 0.f; }
}

// ---------------- CSR build ----------------
__global__ void csr_zero() {
    int i = blockIdx.x * blockDim.x + threadIdx.x;
    if (i < NN) g_deg[i] = 0;
}

__global__ void csr_hist(const int* __restrict__ ei) {
    int e = blockIdx.x * blockDim.x + threadIdx.x;
    if (e < EE) atomicAdd(&g_deg[ei[EE + e]], 1);
}

__global__ void scanA() {
    __shared__ int s[SCAN_BLK];
    int b = blockIdx.x, t = threadIdx.x;
    int i = b * SCAN_BLK + t;
    int v = (i < NN) ? g_deg[i] : 0;
    s[t] = v;
    __syncthreads();
#pragma unroll
    for (int off = 1; off < SCAN_BLK; off <<= 1) {
        int u = (t >= off) ? s[t - off] : 0;
        __syncthreads();
        s[t] += u;
        __syncthreads();
    }
    if (i < NN) g_rowptr[i] = s[t] - v;          // local exclusive
    if (t == SCAN_BLK - 1) g_bsum[b] = s[t];     // block total
}

__global__ void scanB() {
    __shared__ int s[256];
    int t = threadIdx.x;
    int v = (t < NBLK_SCAN) ? g_bsum[t] : 0;
    s[t] = v;
    __syncthreads();
#pragma unroll
    for (int off = 1; off < 256; off <<= 1) {
        int u = (t >= off) ? s[t - off] : 0;
        __syncthreads();
        s[t] += u;
        __syncthreads();
    }
    if (t < NBLK_SCAN) g_boff[t] = s[t] - v;     // exclusive block offsets
}

__global__ void scanC() {
    int i = blockIdx.x * blockDim.x + threadIdx.x;
    if (i < NN) {
        int r = g_rowptr[i] + g_boff[i / SCAN_BLK];
        g_rowptr[i] = r;
        g_cursor[i] = r;
    }
    if (i == 0) g_rowptr[NN] = EE;
}

__global__ void csr_fill(const int* __restrict__ ei) {
    int e = blockIdx.x * blockDim.x + threadIdx.x;
    if (e < EE) {
        int dst = ei[EE + e];
        int pos = atomicAdd(&g_cursor[dst], 1);
        g_csr_src[pos] = ei[e];
    }
}

// ---------------- aggregation: z[i] = h[i] + sum_{j in N(i)} h[j] ----------
// one warp per node; each lane owns a float4 chunk of the 128-dim row
__global__ void gather_agg() {
    long tid = (long)blockIdx.x * blockDim.x + threadIdx.x;
    int node = (int)(tid >> 5);
    if (node >= NN) return;
    int c = (int)(tid & 31) << 2;
    float4 acc = *(const float4*)&g_h[(size_t)node * DD + c];
    int lo = __ldg(&g_rowptr[node]);
    int hi = __ldg(&g_rowptr[node + 1]);
    int j = lo;
    int s_next = (j < hi) ? __ldg(&g_csr_src[j]) : 0;
    while (j < hi) {
        int s = s_next;
        ++j;
        if (j < hi) s_next = __ldg(&g_csr_src[j]);
        float4 v = *(const float4*)&g_h[(size_t)s * DD + c];
        acc.x += v.x; acc.y += v.y; acc.z += v.z; acc.w += v.w;
    }
    *(float4*)&g_z[(size_t)node * DD + c] = acc;
}

// ---------------- fused GEMM (f32x2 packed FMA) ----------------
// MODE 0: C(g_y) = A(g_z) @ B + bias, epilogue accumulates per-column sum/sumsq
// MODE 1: A' = elu(g_y * scale + shift) on load; C(g_h) = elu(A' @ B + bias)
// Tile: BM=128, BN=128, BK=16, 256 threads, 8x8 microtile split {q*4, 64+q*4}.
template <int MODE>
__global__ __launch_bounds__(256) void gemm_kernel(const float* __restrict__ B,
                                                   const float* __restrict__ bias) {
    __shared__ float As[16][132];     // transposed A tile, padded
    __shared__ float Bs[16][132];
    __shared__ float s_sum[DD];
    __shared__ float s_sq[DD];

    const float* A = (MODE == 0) ? g_z : g_y;
    float* C = (MODE == 0) ? g_y : g_h;

    const int tid = threadIdx.x;
    const int tm = tid >> 4;        // 0..15
    const int tn = tid & 15;        // 0..15
    const int rowBase = blockIdx.x * 128;

    if (MODE == 0 && tid < DD) { s_sum[tid] = 0.f; s_sq[tid] = 0.f; }

    // acc2[i][j2]: row i (0..7), column pair j2 (0..3) packed f32x2
    ull acc2[8][4];
#pragma unroll
    for (int i = 0; i < 8; i++)
#pragma unroll
        for (int j = 0; j < 4; j++) acc2[i][j] = 0ull;

    for (int k0 = 0; k0 < DD; k0 += 16) {
        // load A tile (128 rows x 16 k), transpose into As[k][row]
#pragma unroll
        for (int i = 0; i < 2; i++) {
            int f = tid + i * 256;          // 0..511
            int r = f >> 2;                 // 0..127
            int c4 = (f & 3) << 2;          // 0,4,8,12
            int gr = rowBase + r;
            float4 v = make_float4(0.f, 0.f, 0.f, 0.f);
            if (gr < NN) {
                v = *(const float4*)&A[(size_t)gr * DD + k0 + c4];
                if (MODE == 1) {
                    int col = k0 + c4;
                    v.x = elu_f(v.x * g_scale[col + 0] + g_shift[col + 0]);
                    v.y = elu_f(v.y * g_scale[col + 1] + g_shift[col + 1]);
                    v.z = elu_f(v.z * g_scale[col + 2] + g_shift[col + 2]);
                    v.w = elu_f(v.w * g_scale[col + 3] + g_shift[col + 3]);
                }
            }
            As[c4 + 0][r] = v.x;
            As[c4 + 1][r] = v.y;
            As[c4 + 2][r] = v.z;
            As[c4 + 3][r] = v.w;
        }
        // load B tile (16 k x 128 n)
#pragma unroll
        for (int i = 0; i < 2; i++) {
            int f = tid + i * 256;          // 0..511
            int r = f >> 5;                 // 0..15
            int c4 = (f & 31) << 2;
            *(float4*)&Bs[r][c4] = *(const float4*)&B[(size_t)(k0 + r) * DD + c4];
        }
        __syncthreads();

#pragma unroll
        for (int kk = 0; kk < 16; kk++) {
            float4 a0 = *(float4*)&As[kk][tm * 4];
            float4 a1 = *(float4*)&As[kk][64 + tm * 4];
            float a[8] = {a0.x, a0.y, a0.z, a0.w, a1.x, a1.y, a1.z, a1.w};
            ull bp[4];
            bp[0] = *(const ull*)&Bs[kk][tn * 4];
            bp[1] = *(const ull*)&Bs[kk][tn * 4 + 2];
            bp[2] = *(const ull*)&Bs[kk][64 + tn * 4];
            bp[3] = *(const ull*)&Bs[kk][64 + tn * 4 + 2];
#pragma unroll
            for (int i = 0; i < 8; i++) {
                ull ad;
                unsigned ai = __float_as_uint(a[i]);
                asm("mov.b64 %0, {%1, %1};" : "=l"(ad) : "r"(ai));
#pragma unroll
                for (int j = 0; j < 4; j++) {
                    asm("fma.rn.f32x2 %0, %1, %2, %0;"
                        : "+l"(acc2[i][j]) : "l"(ad), "l"(bp[j]));
                }
            }
        }
        __syncthreads();
    }

    // unpack accumulators: o[i][j], j = 0..7 over cols {tn*4+j} and {64+tn*4+j-4}
    float bv[8];
#pragma unroll
    for (int j = 0; j < 8; j++) {
        int col = (j < 4) ? (tn * 4 + j) : (64 + tn * 4 + j - 4);
        bv[j] = bias[col];
    }

    if (MODE == 0) {
        float ps[8], pq[8];
#pragma unroll
        for (int j = 0; j < 8; j++) { ps[j] = 0.f; pq[j] = 0.f; }
#pragma unroll
        for (int i = 0; i < 8; i++) {
            int gr = rowBase + ((i < 4) ? (tm * 4 + i) : (64 + tm * 4 + i - 4));
            if (gr < NN) {
                float o[8];
#pragma unroll
                for (int j2 = 0; j2 < 4; j2++) {
                    unsigned lo, hi;
                    asm("mov.b64 {%0, %1}, %2;" : "=r"(lo), "=r"(hi) : "l"(acc2[i][j2]));
                    o[j2 * 2 + 0] = __uint_as_float(lo) + bv[j2 * 2 + 0];
                    o[j2 * 2 + 1] = __uint_as_float(hi) + bv[j2 * 2 + 1];
                }
#pragma unroll
                for (int j = 0; j < 8; j++) {
                    ps[j] += o[j];
                    pq[j] += o[j] * o[j];
                }
                *(float4*)&C[(size_t)gr * DD + tn * 4]      = make_float4(o[0], o[1], o[2], o[3]);
                *(float4*)&C[(size_t)gr * DD + 64 + tn * 4] = make_float4(o[4], o[5], o[6], o[7]);
            }
        }
#pragma unroll
        for (int j = 0; j < 8; j++) {
            int col = (j < 4) ? (tn * 4 + j) : (64 + tn * 4 + j - 4);
            atomicAdd(&s_sum[col], ps[j]);
            atomicAdd(&s_sq[col], pq[j]);
        }
        __syncthreads();
        if (tid < DD) {
            atomicAdd(&g_colsum[tid], s_sum[tid]);
            atomicAdd(&g_colsumsq[tid], s_sq[tid]);
        }
    } else {
#pragma unroll
        for (int i = 0; i < 8; i++) {
            int gr = rowBase + ((i < 4) ? (tm * 4 + i) : (64 + tm * 4 + i - 4));
            if (gr < NN) {
                float o[8];
#pragma unroll
                for (int j2 = 0; j2 < 4; j2++) {
                    unsigned lo, hi;
                    asm("mov.b64 {%0, %1}, %2;" : "=r"(lo), "=r"(hi) : "l"(acc2[i][j2]));
                    o[j2 * 2 + 0] = elu_f(__uint_as_float(lo) + bv[j2 * 2 + 0]);
                    o[j2 * 2 + 1] = elu_f(__uint_as_float(hi) + bv[j2 * 2 + 1]);
                }
                *(float4*)&C[(size_t)gr * DD + tn * 4]      = make_float4(o[0], o[1], o[2], o[3]);
                *(float4*)&C[(size_t)gr * DD + 64 + tn * 4] = make_float4(o[4], o[5], o[6], o[7]);
            }
        }
    }
}

// ---------------- BN finalize: per-column scale/shift ----------------
__global__ void bn_finalize(const float* __restrict__ gamma, const float* __restrict__ beta) {
    int t = threadIdx.x;
    if (t >= DD) return;
    float mu = g_colsum[t] / (float)NN;
    float var = fmaxf(g_colsumsq[t] / (float)NN - mu * mu, 0.f);
    float rs = rsqrtf(var + BN_EPS);
    float sc = rs * gamma[t];
    g_scale[t] = sc;
    g_shift[t] = beta[t] - mu * sc;
}

// ---------------- pooling + head: batch is sorted -> contiguous ranges ----
__device__ __forceinline__ int lower_bound_dev(const int* a, int n, int key) {
    int lo = 0, hi = n;
    while (lo < hi) {
        int mid = (lo + hi) >> 1;
        if (a[mid] < key) lo = mid + 1; else hi = mid;
    }
    return lo;
}

__global__ void pool_final(const int* __restrict__ batch,
                           const float* __restrict__ linW,
                           const float* __restrict__ linb,
                           float* __restrict__ out) {
    int g = blockIdx.x;
    int t = threadIdx.x;  // 128 threads, t = channel
    int lo = lower_bound_dev(batch, NN, g);
    int hi = lower_bound_dev(batch, NN, g + 1);
    float acc = 0.f;
    for (int r = lo; r < hi; ++r) acc += g_h[(size_t)r * DD + t];
    float cnt = fmaxf((float)(hi - lo), 1.f);
    float p = acc / cnt;
    float v0 = p * __ldg(&linW[t * 2 + 0]);
    float v1 = p * __ldg(&linW[t * 2 + 1]);
#pragma unroll
    for (int o = 16; o > 0; o >>= 1) {
        v0 += __shfl_down_sync(0xffffffffu, v0, o);
        v1 += __shfl_down_sync(0xffffffffu, v1, o);
    }
    __shared__ float s0[4], s1[4];
    if ((t & 31) == 0) { s0[t >> 5] = v0; s1[t >> 5] = v1; }
    __syncthreads();
    if (t == 0) {
        out[g * 2 + 0] = s0[0] + s0[1] + s0[2] + s0[3] + linb[0];
        out[g * 2 + 1] = s1[0] + s1[1] + s1[2] + s1[3] + linb[1];
    }
}

// ---------------- launch ----------------
extern "C" void kernel_launch(void* const* d_in, const int* in_sizes, int n_in,
                              void* d_out, int out_size) {
    const float* x     = (const float*)d_in[0];
    const int*   ei    = (const int*)d_in[1];
    const int*   batch = (const int*)d_in[2];
    const float* W1    = (const float*)d_in[3];
    const float* b1    = (const float*)d_in[4];
    const float* gamma = (const float*)d_in[5];
    const float* beta  = (const float*)d_in[6];
    const float* W2    = (const float*)d_in[7];
    const float* b2    = (const float*)d_in[8];
    const float* linW  = (const float*)d_in[9];
    const float* linb  = (const float*)d_in[10];
    float* out = (float*)d_out;

    const int copyBlocks = (NN * DD / 4 + 255) / 256;
    const int gemmBlocks = (NN + 127) / 128;
    const int nodeBlocks = (NN + 255) / 256;
    const int edgeBlocks = (EE + 255) / 256;
    const int aggBlocks  = (int)(((long)NN * 32 + 255) / 256);

    copy_x_to_h<<<copyBlocks, 256>>>((const float4*)x);

    // build CSR (dst -> list of src)
    csr_zero<<<nodeBlocks, 256>>>();
    csr_hist<<<edgeBlocks, 256>>>(ei);
    scanA<<<NBLK_SCAN, SCAN_BLK>>>();
    scanB<<<1, 256>>>();
    scanC<<<nodeBlocks, 256>>>();
    csr_fill<<<edgeBlocks, 256>>>(ei);

    for (int l = 0; l < LL; l++) {
        gather_agg<<<aggBlocks, 256>>>();
        zero_stats<<<1, 256>>>();
        gemm_kernel<0><<<gemmBlocks, 256>>>(W1 + (size_t)l * DD * DD, b1 + l * DD);
        bn_finalize<<<1, 128>>>(gamma + l * DD, beta + l * DD);
        gemm_kernel<1><<<gemmBlocks, 256>>>(W2 + (size_t)l * DD * DD, b2 + l * DD);
    }

    pool_final<<<GG, 128>>>(batch, linW, linb, out);
}